// round 2
// baseline (speedup 1.0000x reference)
#include <cuda_runtime.h>
#include <mma.h>

using namespace nvcuda;

#define N_NODES   100000
#define NODES_PAD 100096            // 782 * 128
#define N_EDGES   1600000
#define HID       128
#define NGRAPH    1024
#define LN_EPS    1e-5f
#define SCAN_PAD  100352            // 98 * 1024
#define SMW       132               // padded smem row stride (floats)

// ---------------- scratch (static __device__, allocation-free) ----------------
__device__ float  g_h[NODES_PAD * HID];    // node features (fp32, in-place LN update)
__device__ float  g_u[NODES_PAD * HID];    // agg + h (GEMM1 input); pad rows stay 0 forever
__device__ float4 g_rec[N_EDGES];          // per-edge packed: ea0,ea1,ea2,src(bits)
__device__ int    g_deg[N_NODES];
__device__ int    g_inc[SCAN_PAD];
__device__ int    g_bsum[128];
__device__ int    g_boff[128];
__device__ int    g_rowptr[N_NODES + 1];
__device__ int    g_cursor[N_NODES];
__device__ float  g_pooled[NGRAPH * HID];

// ---------------- CSR build ----------------
__global__ void k_zero() {
    int i = blockIdx.x * blockDim.x + threadIdx.x;
    if (i < N_NODES) { g_deg[i] = 0; g_cursor[i] = 0; }
}

__global__ void k_hist(const int* __restrict__ ei) {
    int e = blockIdx.x * blockDim.x + threadIdx.x;
    if (e < N_EDGES) atomicAdd(&g_deg[ei[N_EDGES + e]], 1);
}

__global__ void k_scanA() {
    __shared__ int s[1024];
    int t = threadIdx.x;
    int i = blockIdx.x * 1024 + t;
    int v = (i < N_NODES) ? g_deg[i] : 0;
    s[t] = v;
    __syncthreads();
    for (int off = 1; off < 1024; off <<= 1) {
        int w = (t >= off) ? s[t - off] : 0;
        __syncthreads();
        s[t] += w;
        __syncthreads();
    }
    g_inc[i] = s[t];
    if (t == 1023) g_bsum[blockIdx.x] = s[1023];
}

__global__ void k_scanB() {
    int acc = 0;
    for (int b = 0; b < 98; b++) { g_boff[b] = acc; acc += g_bsum[b]; }
}

__global__ void k_scanC() {
    int i = blockIdx.x * blockDim.x + threadIdx.x;
    if (i < N_NODES) {
        g_rowptr[i + 1] = g_inc[i] + g_boff[i >> 10];
        if (i == 0) g_rowptr[0] = 0;
    }
}

__global__ void k_scatter(const int* __restrict__ ei, const float* __restrict__ ea) {
    int e = blockIdx.x * blockDim.x + threadIdx.x;
    if (e >= N_EDGES) return;
    int s = ei[e];
    int d = ei[N_EDGES + e];
    int p = g_rowptr[d] + atomicAdd(&g_cursor[d], 1);
    const float* a = ea + (long long)e * 3;
    g_rec[p] = make_float4(a[0], a[1], a[2], __int_as_float(s));
}

// ---------------- input projection: h = x @ inW + inb ----------------
__global__ void k_inproj(const float* __restrict__ x, const float* __restrict__ inW,
                         const float* __restrict__ inb) {
    int idx = blockIdx.x * blockDim.x + threadIdx.x;
    if (idx >= N_NODES * HID) return;
    int n = idx >> 7, j = idx & 127;
    const float* xr = x + n * 7;
    float s = inb[j];
#pragma unroll
    for (int k = 0; k < 7; k++) s = fmaf(xr[k], inW[k * HID + j], s);
    g_h[idx] = s;
}

// ---------------- edge aggregation (one warp per node, zero atomics) ----------------
// u[n] = h[n] + sum_{e: dst=n} relu( h[src_e] + edge_attr_e @ edgeW + edgeb )
__global__ void k_edge_agg(const float* __restrict__ edgeW_l, const float* __restrict__ edgeb_l) {
    __shared__ float sw[512];   // W rows k=0..2 at [k*128+j], bias at [384+j]
    for (int i = threadIdx.x; i < 512; i += blockDim.x)
        sw[i] = (i < 384) ? edgeW_l[i] : edgeb_l[i - 384];
    __syncthreads();

    int warp = threadIdx.x >> 5, lane = threadIdx.x & 31;
    int n = blockIdx.x * 8 + warp;
    if (n >= N_NODES) return;

    int r0 = g_rowptr[n], r1 = g_rowptr[n + 1];
    float acc[4];
#pragma unroll
    for (int q = 0; q < 4; q++) acc[q] = g_h[n * HID + lane + 32 * q];

    float4 rec;
    if (r0 < r1) rec = g_rec[r0];
    for (int e = r0; e < r1; e++) {
        float4 nxt;
        if (e + 1 < r1) nxt = g_rec[e + 1];    // prefetch next record
        int src = __float_as_int(rec.w);
        const float* hs = g_h + (size_t)src * HID;
        float hv[4];
#pragma unroll
        for (int q = 0; q < 4; q++) hv[q] = hs[lane + 32 * q];
#pragma unroll
        for (int q = 0; q < 4; q++) {
            int j = lane + 32 * q;
            float m = fmaf(rec.x, sw[j],
                      fmaf(rec.y, sw[128 + j],
                      fmaf(rec.z, sw[256 + j], sw[384 + j])));
            acc[q] += fmaxf(m + hv[q], 0.f);
        }
        rec = nxt;
    }
#pragma unroll
    for (int q = 0; q < 4; q++) g_u[n * HID + lane + 32 * q] = acc[q];
}

// ---------------- fused per-layer MLP: GEMM1+relu -> GEMM2 -> residual+LN ----------------
// Block = 128 rows, 8 warps (16 rows each). W1, W2 staged in smem (tf32), t kept in smem.
__global__ void k_layer(const float* __restrict__ W1, const float* __restrict__ b1,
                        const float* __restrict__ W2, const float* __restrict__ b2,
                        const float* __restrict__ gamma, const float* __restrict__ beta) {
    extern __shared__ float smem[];
    float* w1s = smem;                       // 128 * SMW  (later reused as GEMM2 stage)
    float* w2s = smem + 128 * SMW;
    float* t_s = smem + 2 * 128 * SMW;

    int tid = threadIdx.x;
    for (int idx = tid; idx < HID * HID; idx += blockDim.x) {
        int r = idx >> 7, c = idx & 127;
        w1s[r * SMW + c] = wmma::__float_to_tf32(W1[idx]);
        w2s[r * SMW + c] = wmma::__float_to_tf32(W2[idx]);
    }
    __syncthreads();

    int warp = tid >> 5, lane = tid & 31;
    int row0 = blockIdx.x * 128 + warp * 16;

    wmma::fragment<wmma::accumulator, 16, 16, 8, float> acc[8];
    wmma::fragment<wmma::matrix_a, 16, 16, 8, wmma::precision::tf32, wmma::row_major> a;
    wmma::fragment<wmma::matrix_b, 16, 16, 8, wmma::precision::tf32, wmma::row_major> b;

    // ---- GEMM1: t = relu(u @ W1 + b1) ----
#pragma unroll
    for (int n = 0; n < 8; n++) wmma::fill_fragment(acc[n], 0.f);
    for (int k0 = 0; k0 < HID; k0 += 8) {
        wmma::load_matrix_sync(a, g_u + (size_t)row0 * HID + k0, HID);
#pragma unroll
        for (int i = 0; i < a.num_elements; i++) a.x[i] = wmma::__float_to_tf32(a.x[i]);
#pragma unroll
        for (int n = 0; n < 8; n++) {
            wmma::load_matrix_sync(b, w1s + k0 * SMW + n * 16, SMW);
            wmma::mma_sync(acc[n], a, b, acc[n]);
        }
    }
#pragma unroll
    for (int n = 0; n < 8; n++)
        wmma::store_matrix_sync(t_s + (warp * 16) * SMW + n * 16, acc[n], SMW, wmma::mem_row_major);
    __syncwarp();
    for (int e = lane; e < 16 * HID; e += 32) {           // bias + relu + tf32 round
        int r = e >> 7, c = e & 127;
        float v = t_s[(warp * 16 + r) * SMW + c] + b1[c];
        t_s[(warp * 16 + r) * SMW + c] = wmma::__float_to_tf32(fmaxf(v, 0.f));
    }
    __syncthreads();   // everyone done reading w1s (reused as stage below)

    // ---- GEMM2: g = t @ W2 ----
#pragma unroll
    for (int n = 0; n < 8; n++) wmma::fill_fragment(acc[n], 0.f);
    for (int k0 = 0; k0 < HID; k0 += 8) {
        wmma::load_matrix_sync(a, t_s + (warp * 16) * SMW + k0, SMW);
#pragma unroll
        for (int n = 0; n < 8; n++) {
            wmma::load_matrix_sync(b, w2s + k0 * SMW + n * 16, SMW);
            wmma::mma_sync(acc[n], a, b, acc[n]);
        }
    }
    float* stage = w1s;   // reuse
#pragma unroll
    for (int n = 0; n < 8; n++)
        wmma::store_matrix_sync(stage + (warp * 16) * SMW + n * 16, acc[n], SMW, wmma::mem_row_major);
    __syncwarp();

    // ---- residual + LayerNorm, in-place h update ----
    for (int r = 0; r < 16; r++) {
        int grow = row0 + r;
        if (grow >= N_NODES) break;
        float v[4];
        float s = 0.f, s2 = 0.f;
#pragma unroll
        for (int q = 0; q < 4; q++) {
            int j = lane + 32 * q;
            float gg = stage[(warp * 16 + r) * SMW + j] + b2[j];
            float val = g_h[(size_t)grow * HID + j] + fmaxf(gg, 0.f);
            v[q] = val; s += val; s2 += val * val;
        }
#pragma unroll
        for (int off = 16; off; off >>= 1) {
            s  += __shfl_xor_sync(0xffffffffu, s, off);
            s2 += __shfl_xor_sync(0xffffffffu, s2, off);
        }
        float mu = s * (1.f / HID);
        float var = s2 * (1.f / HID) - mu * mu;
        float rstd = rsqrtf(var + LN_EPS);
#pragma unroll
        for (int q = 0; q < 4; q++) {
            int j = lane + 32 * q;
            g_h[(size_t)grow * HID + j] = (v[q] - mu) * rstd * gamma[j] + beta[j];
        }
    }
}

// ---------------- global mean pool (batch sorted -> binary search) ----------------
__device__ __forceinline__ int lbound(const int* a, int n, int key) {
    int lo = 0, hi = n;
    while (lo < hi) { int m = (lo + hi) >> 1; if (a[m] < key) lo = m + 1; else hi = m; }
    return lo;
}

__global__ void k_pool(const int* __restrict__ batch) {
    int g = blockIdx.x, t = threadIdx.x;
    __shared__ int slo, shi;
    if (t == 0) { slo = lbound(batch, N_NODES, g); shi = lbound(batch, N_NODES, g + 1); }
    __syncthreads();
    int lo = slo, hi = shi;
    float s = 0.f;
    for (int n = lo; n < hi; n++) s += g_h[(size_t)n * HID + t];
    float cnt = (float)(hi - lo);
    g_pooled[g * HID + t] = s / fmaxf(cnt, 1.f);
}

// ---------------- MLP head ----------------
__global__ void k_head(const float* __restrict__ W1, const float* __restrict__ b1,
                       const float* __restrict__ W2, const float* __restrict__ b2,
                       const float* __restrict__ W3, const float* __restrict__ b3,
                       float* __restrict__ out) {
    int g = blockIdx.x, t = threadIdx.x;
    __shared__ float p[HID], o1[HID], o2[64], red[64];
    p[t] = g_pooled[g * HID + t];
    __syncthreads();
    float s = b1[t];
    for (int k = 0; k < HID; k++) s = fmaf(p[k], W1[k * HID + t], s);
    o1[t] = fmaxf(s, 0.f);
    __syncthreads();
    if (t < 64) {
        float s2 = b2[t];
        for (int k = 0; k < HID; k++) s2 = fmaf(o1[k], W2[k * 64 + t], s2);
        o2[t] = fmaxf(s2, 0.f);
    }
    __syncthreads();
    if (t < 64) red[t] = o2[t] * W3[t];
    __syncthreads();
    if (t < 32) {
        float v = red[t] + red[t + 32];
#pragma unroll
        for (int off = 16; off; off >>= 1) v += __shfl_down_sync(0xffffffffu, v, off);
        if (t == 0) out[g] = v + b3[0];
    }
}

// ---------------- launch ----------------
extern "C" void kernel_launch(void* const* d_in, const int* in_sizes, int n_in,
                              void* d_out, int out_size) {
    const float* x     = (const float*)d_in[0];
    const int*   ei    = (const int*)  d_in[1];
    const float* ea    = (const float*)d_in[2];
    const int*   batch = (const int*)  d_in[3];
    const float* inW   = (const float*)d_in[4];
    const float* inb   = (const float*)d_in[5];
    const float* edgeW = (const float*)d_in[6];
    const float* edgeb = (const float*)d_in[7];
    const float* w1    = (const float*)d_in[8];
    const float* b1    = (const float*)d_in[9];
    const float* w2    = (const float*)d_in[10];
    const float* b2    = (const float*)d_in[11];
    const float* gamma = (const float*)d_in[12];
    const float* beta  = (const float*)d_in[13];
    const float* fcW1  = (const float*)d_in[14];
    const float* fcb1  = (const float*)d_in[15];
    const float* fcW2  = (const float*)d_in[16];
    const float* fcb2  = (const float*)d_in[17];
    const float* fcW3  = (const float*)d_in[18];
    const float* fcb3  = (const float*)d_in[19];
    float* out = (float*)d_out;

    const int SMEM_BYTES = 3 * 128 * SMW * sizeof(float);   // 202,752 B
    cudaFuncSetAttribute(k_layer, cudaFuncAttributeMaxDynamicSharedMemorySize, SMEM_BYTES);

    k_zero<<<(N_NODES + 255) / 256, 256>>>();
    k_hist<<<(N_EDGES + 255) / 256, 256>>>(ei);
    k_scanA<<<98, 1024>>>();
    k_scanB<<<1, 1>>>();
    k_scanC<<<(N_NODES + 255) / 256, 256>>>();
    k_scatter<<<(N_EDGES + 255) / 256, 256>>>(ei, ea);
    k_inproj<<<(N_NODES * HID + 255) / 256, 256>>>(x, inW, inb);

    for (int l = 0; l < 4; l++) {
        k_edge_agg<<<(N_NODES + 7) / 8, 256>>>(edgeW + l * 3 * HID, edgeb + l * HID);
        k_layer<<<NODES_PAD / 128, 256, SMEM_BYTES>>>(w1 + l * HID * HID, b1 + l * HID,
                                                      w2 + l * HID * HID, b2 + l * HID,
                                                      gamma + l * HID, beta + l * HID);
    }

    k_pool<<<NGRAPH, 128>>>(batch);
    k_head<<<NGRAPH, 128>>>(fcW1, fcb1, fcW2, fcb2, fcW3, fcb3, out);
}

// round 4
// speedup vs baseline: 1.0461x; 1.0461x over previous
#include <cuda_runtime.h>
#include <mma.h>

using namespace nvcuda;

#define N_NODES   100000
#define NODES_PAD 100096            // 782 * 128 (also mult of 64)
#define N_EDGES   1600000
#define HID       128
#define NGRAPH    1024
#define LN_EPS    1e-5f
#define SCAN_PAD  100352            // 98 * 1024
#define LAYERS    4

// ---------------- scratch (static __device__, allocation-free) ----------------
__device__ float  g_h[NODES_PAD * HID];    // node features fp32 (residual path stays exact)
__device__ float  g_u[NODES_PAD * HID];    // agg + h, tf32-rounded (GEMM1 A); pad rows stay 0
__device__ float  g_t[NODES_PAD * HID];    // relu(u@W1+b1), tf32-rounded (GEMM2 A); pad rows 0
__device__ float  g_w1t[LAYERS * HID * HID];  // tf32-rounded weights
__device__ float  g_w2t[LAYERS * HID * HID];
__device__ float4 g_rec[N_EDGES];          // packed edge: ea0,ea1,ea2,src(bits)
__device__ int    g_deg[N_NODES];
__device__ int    g_inc[SCAN_PAD];
__device__ int    g_bsum[128];
__device__ int    g_rowptr[N_NODES + 1];
__device__ int    g_cursor[N_NODES];
__device__ float  g_pooled[NGRAPH * HID];

// ---------------- CSR build ----------------
__global__ void k_zero() {
    int i = blockIdx.x * blockDim.x + threadIdx.x;
    if (i < N_NODES) { g_deg[i] = 0; g_cursor[i] = 0; }
}

__global__ void k_hist(const int* __restrict__ ei) {
    int e = blockIdx.x * blockDim.x + threadIdx.x;
    if (e < N_EDGES) atomicAdd(&g_deg[ei[N_EDGES + e]], 1);
}

__global__ void k_scanA() {
    __shared__ int s[1024];
    int t = threadIdx.x;
    int i = blockIdx.x * 1024 + t;
    int v = (i < N_NODES) ? g_deg[i] : 0;
    s[t] = v;
    __syncthreads();
    for (int off = 1; off < 1024; off <<= 1) {
        int w = (t >= off) ? s[t - off] : 0;
        __syncthreads();
        s[t] += w;
        __syncthreads();
    }
    g_inc[i] = s[t];
    if (t == 1023) g_bsum[blockIdx.x] = s[1023];
}

// fused scanB+scanC: blocks of 256 lie inside one 1024-chunk -> block-uniform offset
__global__ void k_scanBC() {
    __shared__ int soff;
    int i = blockIdx.x * 256 + threadIdx.x;
    if (threadIdx.x == 0) {
        int chunk = blockIdx.x >> 2;      // i >> 10
        int acc = 0;
        for (int b = 0; b < chunk; b++) acc += g_bsum[b];
        soff = acc;
    }
    __syncthreads();
    if (i < N_NODES) {
        g_rowptr[i + 1] = g_inc[i] + soff;
        if (i == 0) g_rowptr[0] = 0;
    }
}

__global__ void k_scatter(const int* __restrict__ ei, const float* __restrict__ ea) {
    int e = blockIdx.x * blockDim.x + threadIdx.x;
    if (e >= N_EDGES) return;
    int s = ei[e];
    int d = ei[N_EDGES + e];
    int p = g_rowptr[d] + atomicAdd(&g_cursor[d], 1);
    const float* a = ea + (long long)e * 3;
    g_rec[p] = make_float4(a[0], a[1], a[2], __int_as_float(s));
}

// ---------------- weight pre-rounding to tf32 (once per call) ----------------
__global__ void k_prep(const float* __restrict__ w1, const float* __restrict__ w2) {
    int i = blockIdx.x * blockDim.x + threadIdx.x;
    if (i < LAYERS * HID * HID) {
        g_w1t[i] = wmma::__float_to_tf32(w1[i]);
        g_w2t[i] = wmma::__float_to_tf32(w2[i]);
    }
}

// ---------------- input projection: h = x @ inW + inb ----------------
__global__ void k_inproj(const float* __restrict__ x, const float* __restrict__ inW,
                         const float* __restrict__ inb) {
    int idx = blockIdx.x * blockDim.x + threadIdx.x;
    if (idx >= N_NODES * HID) return;
    int n = idx >> 7, j = idx & 127;
    const float* xr = x + n * 7;
    float s = inb[j];
#pragma unroll
    for (int k = 0; k < 7; k++) s = fmaf(xr[k], inW[k * HID + j], s);
    g_h[idx] = s;
}

// ---------------- edge aggregation (one warp per node, zero atomics) ----------------
// u[n] = tf32round( h[n] + sum_{e: dst=n} relu( h[src_e] + ea_e @ edgeW + edgeb ) )
__global__ void k_edge_agg(const float* __restrict__ edgeW_l, const float* __restrict__ edgeb_l) {
    __shared__ float sw[512];   // W rows k=0..2 at [k*128+j], bias at [384+j]
    for (int i = threadIdx.x; i < 512; i += blockDim.x)
        sw[i] = (i < 384) ? edgeW_l[i] : edgeb_l[i - 384];
    __syncthreads();

    int warp = threadIdx.x >> 5, lane = threadIdx.x & 31;
    int n = blockIdx.x * 8 + warp;
    if (n >= N_NODES) return;

    int r0 = g_rowptr[n], r1 = g_rowptr[n + 1];
    float acc[4];
#pragma unroll
    for (int q = 0; q < 4; q++) acc[q] = g_h[(size_t)n * HID + lane + 32 * q];

    float4 rec;
    if (r0 < r1) rec = g_rec[r0];
    for (int e = r0; e < r1; e++) {
        float4 nxt;
        if (e + 1 < r1) nxt = g_rec[e + 1];    // prefetch next record
        int src = __float_as_int(rec.w);
        const float* hs = g_h + (size_t)src * HID;
        float hv[4];
#pragma unroll
        for (int q = 0; q < 4; q++) hv[q] = hs[lane + 32 * q];
#pragma unroll
        for (int q = 0; q < 4; q++) {
            int j = lane + 32 * q;
            float m = fmaf(rec.x, sw[j],
                      fmaf(rec.y, sw[128 + j],
                      fmaf(rec.z, sw[256 + j], sw[384 + j])));
            acc[q] += fmaxf(m + hv[q], 0.f);
        }
        rec = nxt;
    }
#pragma unroll
    for (int q = 0; q < 4; q++)
        g_u[(size_t)n * HID + lane + 32 * q] = wmma::__float_to_tf32(acc[q]);
}

// ---------------- GEMM1: t = tf32round(relu(u @ W1 + b1)) ----------------
// Weights taken from g_w1t via layer index (device-side symbol access).
__global__ void __launch_bounds__(128) k_gemm_relu(int l, const float* __restrict__ bias) {
    const float* W = g_w1t + l * HID * HID;
    int warp = threadIdx.x >> 5, lane = threadIdx.x & 31;
    int row0 = blockIdx.x * 64 + warp * 16;

    wmma::fragment<wmma::accumulator, 16, 16, 8, float> acc[8];
#pragma unroll
    for (int n = 0; n < 8; n++) wmma::fill_fragment(acc[n], 0.f);

    wmma::fragment<wmma::matrix_a, 16, 16, 8, wmma::precision::tf32, wmma::row_major> a;
    wmma::fragment<wmma::matrix_b, 16, 16, 8, wmma::precision::tf32, wmma::row_major> b;

#pragma unroll 4
    for (int k0 = 0; k0 < HID; k0 += 8) {
        wmma::load_matrix_sync(a, g_u + (size_t)row0 * HID + k0, HID);
#pragma unroll
        for (int n = 0; n < 8; n++) {
            wmma::load_matrix_sync(b, W + k0 * HID + n * 16, HID);
            wmma::mma_sync(acc[n], a, b, acc[n]);
        }
    }

    __shared__ float stage[4][16 * 132];
#pragma unroll
    for (int n = 0; n < 8; n++)
        wmma::store_matrix_sync(&stage[warp][n * 16], acc[n], 132, wmma::mem_row_major);
    __syncwarp();
#pragma unroll
    for (int e = lane; e < 16 * HID; e += 32) {
        int r = e >> 7, c = e & 127;
        float v = stage[warp][r * 132 + c] + bias[c];
        g_t[(size_t)(row0 + r) * HID + c] = wmma::__float_to_tf32(fmaxf(v, 0.f));
    }
}

// ---------------- GEMM2 + residual + LayerNorm (in-place h update) ----------------
__global__ void __launch_bounds__(128) k_gemm_ln(int l, const float* __restrict__ bias,
                                                 const float* __restrict__ gamma,
                                                 const float* __restrict__ beta) {
    const float* W = g_w2t + l * HID * HID;
    int warp = threadIdx.x >> 5, lane = threadIdx.x & 31;
    int row0 = blockIdx.x * 64 + warp * 16;

    wmma::fragment<wmma::accumulator, 16, 16, 8, float> acc[8];
#pragma unroll
    for (int n = 0; n < 8; n++) wmma::fill_fragment(acc[n], 0.f);

    wmma::fragment<wmma::matrix_a, 16, 16, 8, wmma::precision::tf32, wmma::row_major> a;
    wmma::fragment<wmma::matrix_b, 16, 16, 8, wmma::precision::tf32, wmma::row_major> b;

#pragma unroll 4
    for (int k0 = 0; k0 < HID; k0 += 8) {
        wmma::load_matrix_sync(a, g_t + (size_t)row0 * HID + k0, HID);
#pragma unroll
        for (int n = 0; n < 8; n++) {
            wmma::load_matrix_sync(b, W + k0 * HID + n * 16, HID);
            wmma::mma_sync(acc[n], a, b, acc[n]);
        }
    }

    __shared__ float stage[4][16 * 132];
#pragma unroll
    for (int n = 0; n < 8; n++)
        wmma::store_matrix_sync(&stage[warp][n * 16], acc[n], 132, wmma::mem_row_major);
    __syncwarp();

    for (int r = 0; r < 16; r++) {
        int grow = row0 + r;
        if (grow >= N_NODES) break;
        float v[4];
        float s = 0.f, s2 = 0.f;
#pragma unroll
        for (int q = 0; q < 4; q++) {
            int j = lane + 32 * q;
            float gg = stage[warp][r * 132 + j] + bias[j];
            float val = g_h[(size_t)grow * HID + j] + fmaxf(gg, 0.f);
            v[q] = val; s += val; s2 += val * val;
        }
#pragma unroll
        for (int off = 16; off; off >>= 1) {
            s  += __shfl_xor_sync(0xffffffffu, s, off);
            s2 += __shfl_xor_sync(0xffffffffu, s2, off);
        }
        float mu = s * (1.f / HID);
        float var = s2 * (1.f / HID) - mu * mu;
        float rstd = rsqrtf(var + LN_EPS);
#pragma unroll
        for (int q = 0; q < 4; q++) {
            int j = lane + 32 * q;
            g_h[(size_t)grow * HID + j] = (v[q] - mu) * rstd * gamma[j] + beta[j];
        }
    }
}

// ---------------- global mean pool (batch sorted -> binary search) ----------------
__device__ __forceinline__ int lbound(const int* a, int n, int key) {
    int lo = 0, hi = n;
    while (lo < hi) { int m = (lo + hi) >> 1; if (a[m] < key) lo = m + 1; else hi = m; }
    return lo;
}

__global__ void k_pool(const int* __restrict__ batch) {
    int g = blockIdx.x, t = threadIdx.x;
    __shared__ int slo, shi;
    if (t == 0) { slo = lbound(batch, N_NODES, g); shi = lbound(batch, N_NODES, g + 1); }
    __syncthreads();
    int lo = slo, hi = shi;
    float s = 0.f;
    for (int n = lo; n < hi; n++) s += g_h[(size_t)n * HID + t];
    float cnt = (float)(hi - lo);
    g_pooled[g * HID + t] = s / fmaxf(cnt, 1.f);
}

// ---------------- MLP head ----------------
__global__ void k_head(const float* __restrict__ W1, const float* __restrict__ b1,
                       const float* __restrict__ W2, const float* __restrict__ b2,
                       const float* __restrict__ W3, const float* __restrict__ b3,
                       float* __restrict__ out) {
    int g = blockIdx.x, t = threadIdx.x;
    __shared__ float p[HID], o1[HID], o2[64], red[64];
    p[t] = g_pooled[g * HID + t];
    __syncthreads();
    float s = b1[t];
    for (int k = 0; k < HID; k++) s = fmaf(p[k], W1[k * HID + t], s);
    o1[t] = fmaxf(s, 0.f);
    __syncthreads();
    if (t < 64) {
        float s2 = b2[t];
        for (int k = 0; k < HID; k++) s2 = fmaf(o1[k], W2[k * 64 + t], s2);
        o2[t] = fmaxf(s2, 0.f);
    }
    __syncthreads();
    if (t < 64) red[t] = o2[t] * W3[t];
    __syncthreads();
    if (t < 32) {
        float v = red[t] + red[t + 32];
#pragma unroll
        for (int off = 16; off; off >>= 1) v += __shfl_down_sync(0xffffffffu, v, off);
        if (t == 0) out[g] = v + b3[0];
    }
}

// ---------------- launch ----------------
extern "C" void kernel_launch(void* const* d_in, const int* in_sizes, int n_in,
                              void* d_out, int out_size) {
    const float* x     = (const float*)d_in[0];
    const int*   ei    = (const int*)  d_in[1];
    const float* ea    = (const float*)d_in[2];
    const int*   batch = (const int*)  d_in[3];
    const float* inW   = (const float*)d_in[4];
    const float* inb   = (const float*)d_in[5];
    const float* edgeW = (const float*)d_in[6];
    const float* edgeb = (const float*)d_in[7];
    const float* w1    = (const float*)d_in[8];
    const float* b1    = (const float*)d_in[9];
    const float* w2    = (const float*)d_in[10];
    const float* b2    = (const float*)d_in[11];
    const float* gamma = (const float*)d_in[12];
    const float* beta  = (const float*)d_in[13];
    const float* fcW1  = (const float*)d_in[14];
    const float* fcb1  = (const float*)d_in[15];
    const float* fcW2  = (const float*)d_in[16];
    const float* fcb2  = (const float*)d_in[17];
    const float* fcW3  = (const float*)d_in[18];
    const float* fcb3  = (const float*)d_in[19];
    float* out = (float*)d_out;

    k_zero<<<(N_NODES + 255) / 256, 256>>>();
    k_hist<<<(N_EDGES + 255) / 256, 256>>>(ei);
    k_scanA<<<98, 1024>>>();
    k_scanBC<<<(N_NODES + 255) / 256, 256>>>();
    k_scatter<<<(N_EDGES + 255) / 256, 256>>>(ei, ea);
    k_prep<<<(LAYERS * HID * HID + 255) / 256, 256>>>(w1, w2);
    k_inproj<<<(N_NODES * HID + 255) / 256, 256>>>(x, inW, inb);

    for (int l = 0; l < 4; l++) {
        k_edge_agg<<<(N_NODES + 7) / 8, 256>>>(edgeW + l * 3 * HID, edgeb + l * HID);
        k_gemm_relu<<<NODES_PAD / 64, 128>>>(l, b1 + l * HID);
        k_gemm_ln<<<NODES_PAD / 64, 128>>>(l, b2 + l * HID,
                                           gamma + l * HID, beta + l * HID);
    }

    k_pool<<<NGRAPH, 128>>>(batch);
    k_head<<<NGRAPH, 128>>>(fcW1, fcb1, fcW2, fcb2, fcW3, fcb3, out);
}

// round 5
// speedup vs baseline: 1.3650x; 1.3048x over previous
#include <cuda_runtime.h>
#include <mma.h>

using namespace nvcuda;

#define N_NODES   100000
#define NODES_PAD 100096            // 6256 * 16
#define N_TILES   6256              // NODES_PAD / 16
#define N_EDGES   1600000
#define HID       128
#define NGRAPH    1024
#define LN_EPS    1e-5f
#define SCAN_PAD  100352            // 98 * 1024
#define LAYERS    4
#define GGRID     296               // persistent GEMM grid

// ---------------- scratch (static __device__, allocation-free) ----------------
__device__ float  g_h[NODES_PAD * HID];    // node features fp32
__device__ float  g_u[NODES_PAD * HID];    // agg + h (tf32-rounded); pad rows stay 0
__device__ float  g_t[NODES_PAD * HID];    // relu(u@W1+b1) (tf32-rounded)
__device__ float  g_w1t[LAYERS * HID * HID];
__device__ float  g_w2t[LAYERS * HID * HID];
__device__ float4 g_rec[N_EDGES];          // packed edge: ea0,ea1,ea2,src(bits)
__device__ int    g_deg[N_NODES];
__device__ int    g_inc[SCAN_PAD];
__device__ int    g_bsum[128];
__device__ int    g_rowptr[N_NODES + 1];
__device__ int    g_cursor[N_NODES];
__device__ float  g_pooled[NGRAPH * HID];

// ---------------- CSR build ----------------
__global__ void k_zero() {
    int i = blockIdx.x * blockDim.x + threadIdx.x;
    if (i < N_NODES) { g_deg[i] = 0; g_cursor[i] = 0; }
}

__global__ void k_hist(const int* __restrict__ ei) {
    int e = blockIdx.x * blockDim.x + threadIdx.x;
    if (e < N_EDGES) atomicAdd(&g_deg[ei[N_EDGES + e]], 1);
}

__global__ void k_scanA() {
    __shared__ int s[1024];
    int t = threadIdx.x;
    int i = blockIdx.x * 1024 + t;
    int v = (i < N_NODES) ? g_deg[i] : 0;
    s[t] = v;
    __syncthreads();
    for (int off = 1; off < 1024; off <<= 1) {
        int w = (t >= off) ? s[t - off] : 0;
        __syncthreads();
        s[t] += w;
        __syncthreads();
    }
    g_inc[i] = s[t];
    if (t == 1023) g_bsum[blockIdx.x] = s[1023];
}

__global__ void k_scanBC() {
    __shared__ int soff;
    int i = blockIdx.x * 256 + threadIdx.x;
    if (threadIdx.x == 0) {
        int chunk = blockIdx.x >> 2;
        int acc = 0;
        for (int b = 0; b < chunk; b++) acc += g_bsum[b];
        soff = acc;
    }
    __syncthreads();
    if (i < N_NODES) {
        g_rowptr[i + 1] = g_inc[i] + soff;
        if (i == 0) g_rowptr[0] = 0;
    }
}

__global__ void k_scatter(const int* __restrict__ ei, const float* __restrict__ ea) {
    int e = blockIdx.x * blockDim.x + threadIdx.x;
    if (e >= N_EDGES) return;
    int s = ei[e];
    int d = ei[N_EDGES + e];
    int p = g_rowptr[d] + atomicAdd(&g_cursor[d], 1);
    const float* a = ea + (long long)e * 3;
    g_rec[p] = make_float4(a[0], a[1], a[2], __int_as_float(s));
}

// ---------------- weight pre-rounding to tf32 (once per call) ----------------
__global__ void k_prep(const float* __restrict__ w1, const float* __restrict__ w2) {
    int i = blockIdx.x * blockDim.x + threadIdx.x;
    if (i < LAYERS * HID * HID) {
        g_w1t[i] = wmma::__float_to_tf32(w1[i]);
        g_w2t[i] = wmma::__float_to_tf32(w2[i]);
    }
}

// ---------------- input projection: h = x @ inW + inb ----------------
__global__ void k_inproj(const float* __restrict__ x, const float* __restrict__ inW,
                         const float* __restrict__ inb) {
    int idx = blockIdx.x * blockDim.x + threadIdx.x;
    if (idx >= N_NODES * HID) return;
    int n = idx >> 7, j = idx & 127;
    const float* xr = x + n * 7;
    float s = inb[j];
#pragma unroll
    for (int k = 0; k < 7; k++) s = fmaf(xr[k], inW[k * HID + j], s);
    g_h[idx] = s;
}

// ---------------- edge aggregation: warp/node, float4, weights in regs ----------------
// u[n] = tf32round( h[n] + sum_{e: dst=n} relu( h[src_e] + ea_e @ edgeW + edgeb ) )
__global__ void k_edge_agg(const float* __restrict__ edgeW_l, const float* __restrict__ edgeb_l) {
    int warp = threadIdx.x >> 5, lane = threadIdx.x & 31;
    int c0 = lane * 4;
    // per-thread weights for its 4 columns
    float4 w0 = *(const float4*)(edgeW_l + 0 * HID + c0);
    float4 w1 = *(const float4*)(edgeW_l + 1 * HID + c0);
    float4 w2 = *(const float4*)(edgeW_l + 2 * HID + c0);
    float4 bb = *(const float4*)(edgeb_l + c0);

    int n = blockIdx.x * 8 + warp;
    if (n >= N_NODES) return;

    int r0 = g_rowptr[n], r1 = g_rowptr[n + 1];
    float4 acc = *(const float4*)(g_h + (size_t)n * HID + c0);

    float4 rec;
    if (r0 < r1) rec = g_rec[r0];
    for (int e = r0; e < r1; e++) {
        float4 nxt;
        if (e + 1 < r1) nxt = g_rec[e + 1];
        int src = __float_as_int(rec.w);
        float4 hv = *(const float4*)(g_h + (size_t)src * HID + c0);
        float mx = fmaf(rec.x, w0.x, fmaf(rec.y, w1.x, fmaf(rec.z, w2.x, bb.x))) + hv.x;
        float my = fmaf(rec.x, w0.y, fmaf(rec.y, w1.y, fmaf(rec.z, w2.y, bb.y))) + hv.y;
        float mz = fmaf(rec.x, w0.z, fmaf(rec.y, w1.z, fmaf(rec.z, w2.z, bb.z))) + hv.z;
        float mw = fmaf(rec.x, w0.w, fmaf(rec.y, w1.w, fmaf(rec.z, w2.w, bb.w))) + hv.w;
        acc.x += fmaxf(mx, 0.f);
        acc.y += fmaxf(my, 0.f);
        acc.z += fmaxf(mz, 0.f);
        acc.w += fmaxf(mw, 0.f);
        rec = nxt;
    }
    float4 o;
    o.x = wmma::__float_to_tf32(acc.x);
    o.y = wmma::__float_to_tf32(acc.y);
    o.z = wmma::__float_to_tf32(acc.z);
    o.w = wmma::__float_to_tf32(acc.w);
    *(float4*)(g_u + (size_t)n * HID + c0) = o;
}

// ---------------- persistent GEMM1: t = tf32round(relu(u @ W1 + b1)) ----------------
// 8 warps; warp w holds ALL 16 B fragments of its 16-col slice in registers.
#define SMA 136   // smem A/C row stride (floats); 136*4 % 16 == 0

__global__ void __launch_bounds__(256) k_gemm1_p(int l, const float* __restrict__ bias) {
    const float* W = g_w1t + l * HID * HID;
    int tid = threadIdx.x, warp = tid >> 5;

    wmma::fragment<wmma::matrix_b, 16, 16, 8, wmma::precision::tf32, wmma::row_major> bf[16];
#pragma unroll
    for (int k0 = 0; k0 < 16; k0++)
        wmma::load_matrix_sync(bf[k0], W + k0 * 8 * HID + warp * 16, HID);

    __shared__ float As[16 * SMA];
    __shared__ float Cs[16 * SMA];

    float4 bias4 = *(const float4*)(bias + ((tid & 31) * 4) % 0);  // placeholder removed below
    (void)bias4;

    for (int t = blockIdx.x; t < N_TILES; t += gridDim.x) {
        int row0 = t * 16;
        const float4* src = (const float4*)(g_u + (size_t)row0 * HID);
#pragma unroll
        for (int i = tid; i < 512; i += 256) {
            int r = i >> 5, c = i & 31;
            *(float4*)(As + r * SMA + c * 4) = src[i];
        }
        __syncthreads();

        wmma::fragment<wmma::accumulator, 16, 16, 8, float> acc;
        wmma::fragment<wmma::matrix_a, 16, 16, 8, wmma::precision::tf32, wmma::row_major> af;
        wmma::fill_fragment(acc, 0.f);
#pragma unroll
        for (int k0 = 0; k0 < 16; k0++) {
            wmma::load_matrix_sync(af, As + k0 * 8, SMA);
            wmma::mma_sync(acc, af, bf[k0], acc);
        }
        wmma::store_matrix_sync(Cs + warp * 16, acc, SMA, wmma::mem_row_major);
        __syncthreads();

#pragma unroll
        for (int i = tid; i < 512; i += 256) {
            int r = i >> 5, c4 = i & 31;
            float4 v = *(float4*)(Cs + r * SMA + c4 * 4);
            const float* bp = bias + c4 * 4;
            v.x = wmma::__float_to_tf32(fmaxf(v.x + bp[0], 0.f));
            v.y = wmma::__float_to_tf32(fmaxf(v.y + bp[1], 0.f));
            v.z = wmma::__float_to_tf32(fmaxf(v.z + bp[2], 0.f));
            v.w = wmma::__float_to_tf32(fmaxf(v.w + bp[3], 0.f));
            *(float4*)(g_t + (size_t)(row0 + r) * HID + c4 * 4) = v;
        }
        __syncthreads();
    }
}

// ---------------- persistent GEMM2 + residual + LayerNorm ----------------
__global__ void __launch_bounds__(256) k_gemm2_p(int l, const float* __restrict__ bias,
                                                 const float* __restrict__ gamma,
                                                 const float* __restrict__ beta) {
    const float* W = g_w2t + l * HID * HID;
    int tid = threadIdx.x, warp = tid >> 5, lane = tid & 31;

    wmma::fragment<wmma::matrix_b, 16, 16, 8, wmma::precision::tf32, wmma::row_major> bf[16];
#pragma unroll
    for (int k0 = 0; k0 < 16; k0++)
        wmma::load_matrix_sync(bf[k0], W + k0 * 8 * HID + warp * 16, HID);

    int c0 = lane * 4;
    float4 bias4  = *(const float4*)(bias  + c0);
    float4 gam4   = *(const float4*)(gamma + c0);
    float4 bet4   = *(const float4*)(beta  + c0);

    __shared__ float As[16 * SMA];
    __shared__ float Cs[16 * SMA];

    for (int t = blockIdx.x; t < N_TILES; t += gridDim.x) {
        int row0 = t * 16;
        const float4* src = (const float4*)(g_t + (size_t)row0 * HID);
#pragma unroll
        for (int i = tid; i < 512; i += 256) {
            int r = i >> 5, c = i & 31;
            *(float4*)(As + r * SMA + c * 4) = src[i];
        }
        __syncthreads();

        wmma::fragment<wmma::accumulator, 16, 16, 8, float> acc;
        wmma::fragment<wmma::matrix_a, 16, 16, 8, wmma::precision::tf32, wmma::row_major> af;
        wmma::fill_fragment(acc, 0.f);
#pragma unroll
        for (int k0 = 0; k0 < 16; k0++) {
            wmma::load_matrix_sync(af, As + k0 * 8, SMA);
            wmma::mma_sync(acc, af, bf[k0], acc);
        }
        wmma::store_matrix_sync(Cs + warp * 16, acc, SMA, wmma::mem_row_major);
        __syncthreads();

        // residual + LN: warp handles rows {2*warp, 2*warp+1}
#pragma unroll
        for (int s = 0; s < 2; s++) {
            int r = warp * 2 + s;
            int grow = row0 + r;
            float4 cv = *(float4*)(Cs + r * SMA + c0);
            float4 hv = *(const float4*)(g_h + (size_t)grow * HID + c0);
            float4 v;
            v.x = hv.x + fmaxf(cv.x + bias4.x, 0.f);
            v.y = hv.y + fmaxf(cv.y + bias4.y, 0.f);
            v.z = hv.z + fmaxf(cv.z + bias4.z, 0.f);
            v.w = hv.w + fmaxf(cv.w + bias4.w, 0.f);
            float sum = v.x + v.y + v.z + v.w;
            float sq  = v.x * v.x + v.y * v.y + v.z * v.z + v.w * v.w;
#pragma unroll
            for (int off = 16; off; off >>= 1) {
                sum += __shfl_xor_sync(0xffffffffu, sum, off);
                sq  += __shfl_xor_sync(0xffffffffu, sq,  off);
            }
            float mu = sum * (1.f / HID);
            float var = sq * (1.f / HID) - mu * mu;
            float rstd = rsqrtf(var + LN_EPS);
            float4 o;
            o.x = (v.x - mu) * rstd * gam4.x + bet4.x;
            o.y = (v.y - mu) * rstd * gam4.y + bet4.y;
            o.z = (v.z - mu) * rstd * gam4.z + bet4.z;
            o.w = (v.w - mu) * rstd * gam4.w + bet4.w;
            *(float4*)(g_h + (size_t)grow * HID + c0) = o;
        }
        __syncthreads();
    }
}

// ---------------- global mean pool (batch sorted -> binary search) ----------------
__device__ __forceinline__ int lbound(const int* a, int n, int key) {
    int lo = 0, hi = n;
    while (lo < hi) { int m = (lo + hi) >> 1; if (a[m] < key) lo = m + 1; else hi = m; }
    return lo;
}

__global__ void k_pool(const int* __restrict__ batch) {
    int g = blockIdx.x, t = threadIdx.x;
    __shared__ int slo, shi;
    if (t == 0) { slo = lbound(batch, N_NODES, g); shi = lbound(batch, N_NODES, g + 1); }
    __syncthreads();
    int lo = slo, hi = shi;
    float s = 0.f;
    for (int n = lo; n < hi; n++) s += g_h[(size_t)n * HID + t];
    float cnt = (float)(hi - lo);
    g_pooled[g * HID + t] = s / fmaxf(cnt, 1.f);
}

// ---------------- MLP head ----------------
__global__ void k_head(const float* __restrict__ W1, const float* __restrict__ b1,
                       const float* __restrict__ W2, const float* __restrict__ b2,
                       const float* __restrict__ W3, const float* __restrict__ b3,
                       float* __restrict__ out) {
    int g = blockIdx.x, t = threadIdx.x;
    __shared__ float p[HID], o1[HID], o2[64], red[64];
    p[t] = g_pooled[g * HID + t];
    __syncthreads();
    float s = b1[t];
    for (int k = 0; k < HID; k++) s = fmaf(p[k], W1[k * HID + t], s);
    o1[t] = fmaxf(s, 0.f);
    __syncthreads();
    if (t < 64) {
        float s2 = b2[t];
        for (int k = 0; k < HID; k++) s2 = fmaf(o1[k], W2[k * 64 + t], s2);
        o2[t] = fmaxf(s2, 0.f);
    }
    __syncthreads();
    if (t < 64) red[t] = o2[t] * W3[t];
    __syncthreads();
    if (t < 32) {
        float v = red[t] + red[t + 32];
#pragma unroll
        for (int off = 16; off; off >>= 1) v += __shfl_down_sync(0xffffffffu, v, off);
        if (t == 0) out[g] = v + b3[0];
    }
}

// ---------------- launch ----------------
extern "C" void kernel_launch(void* const* d_in, const int* in_sizes, int n_in,
                              void* d_out, int out_size) {
    const float* x     = (const float*)d_in[0];
    const int*   ei    = (const int*)  d_in[1];
    const float* ea    = (const float*)d_in[2];
    const int*   batch = (const int*)  d_in[3];
    const float* inW   = (const float*)d_in[4];
    const float* inb   = (const float*)d_in[5];
    const float* edgeW = (const float*)d_in[6];
    const float* edgeb = (const float*)d_in[7];
    const float* w1    = (const float*)d_in[8];
    const float* b1    = (const float*)d_in[9];
    const float* w2    = (const float*)d_in[10];
    const float* b2    = (const float*)d_in[11];
    const float* gamma = (const float*)d_in[12];
    const float* beta  = (const float*)d_in[13];
    const float* fcW1  = (const float*)d_in[14];
    const float* fcb1  = (const float*)d_in[15];
    const float* fcW2  = (const float*)d_in[16];
    const float* fcb2  = (const float*)d_in[17];
    const float* fcW3  = (const float*)d_in[18];
    const float* fcb3  = (const float*)d_in[19];
    float* out = (float*)d_out;

    k_zero<<<(N_NODES + 255) / 256, 256>>>();
    k_hist<<<(N_EDGES + 255) / 256, 256>>>(ei);
    k_scanA<<<98, 1024>>>();
    k_scanBC<<<(N_NODES + 255) / 256, 256>>>();
    k_scatter<<<(N_EDGES + 255) / 256, 256>>>(ei, ea);
    k_prep<<<(LAYERS * HID * HID + 255) / 256, 256>>>(w1, w2);
    k_inproj<<<(N_NODES * HID + 255) / 256, 256>>>(x, inW, inb);

    for (int l = 0; l < 4; l++) {
        k_edge_agg<<<(N_NODES + 7) / 8, 256>>>(edgeW + l * 3 * HID, edgeb + l * HID);
        k_gemm1_p<<<GGRID, 256>>>(l, b1 + l * HID);
        k_gemm2_p<<<GGRID, 256>>>(l, b2 + l * HID, gamma + l * HID, beta + l * HID);
    }

    k_pool<<<NGRAPH, 128>>>(batch);
    k_head<<<NGRAPH, 128>>>(fcW1, fcb1, fcW2, fcb2, fcW3, fcb3, out);
}

// round 6
// speedup vs baseline: 1.4055x; 1.0297x over previous
#include <cuda_runtime.h>
#include <mma.h>

using namespace nvcuda;

#define N_NODES   100000
#define NODES_PAD 100096            // 6256 * 16
#define N_TILES   6256              // NODES_PAD / 16
#define N_EDGES   1600000
#define HID       128
#define NGRAPH    1024
#define LN_EPS    1e-5f
#define SCAN_PAD  100352            // 98 * 1024
#define LAYERS    4
#define GGRID     296               // persistent GEMM grid
#define SMA       136               // smem A/T/C row stride (floats)
#define SMW2      132               // smem W2 row stride (floats)

// dynamic smem partition (floats): W2s[128*SMW2] | As[16*SMA] | Ts[16*SMA] | Cs[16*SMA]
#define W2S_F     (128 * SMW2)                       // 16896
#define TILE_F    (16 * SMA)                         // 2176
#define SMEM_F    (W2S_F + 3 * TILE_F)               // 23424
#define SMEM_B    (SMEM_F * 4)                       // 93,696 bytes

// ---------------- scratch (static __device__, allocation-free) ----------------
__device__ float  g_h[NODES_PAD * HID];    // node features fp32
__device__ float  g_u[NODES_PAD * HID];    // agg + h (tf32-rounded); pad rows stay 0
__device__ float  g_w1t[LAYERS * HID * HID];
__device__ float  g_w2t[LAYERS * HID * HID];
__device__ float4 g_rec[N_EDGES];          // packed edge: ea0,ea1,ea2,src(bits)
__device__ int    g_deg[N_NODES];
__device__ int    g_inc[SCAN_PAD];
__device__ int    g_bsum[128];
__device__ int    g_rowptr[N_NODES + 1];
__device__ int    g_cursor[N_NODES];
__device__ float  g_pooled[NGRAPH * HID];

// ---------------- CSR build ----------------
__global__ void k_zero() {
    int i = blockIdx.x * blockDim.x + threadIdx.x;
    if (i < N_NODES) { g_deg[i] = 0; g_cursor[i] = 0; }
}

__global__ void k_hist(const int* __restrict__ ei) {
    int e = blockIdx.x * blockDim.x + threadIdx.x;
    if (e < N_EDGES) atomicAdd(&g_deg[ei[N_EDGES + e]], 1);
}

__global__ void k_scanA() {
    __shared__ int s[1024];
    int t = threadIdx.x;
    int i = blockIdx.x * 1024 + t;
    int v = (i < N_NODES) ? g_deg[i] : 0;
    s[t] = v;
    __syncthreads();
    for (int off = 1; off < 1024; off <<= 1) {
        int w = (t >= off) ? s[t - off] : 0;
        __syncthreads();
        s[t] += w;
        __syncthreads();
    }
    g_inc[i] = s[t];
    if (t == 1023) g_bsum[blockIdx.x] = s[1023];
}

__global__ void k_scanBC() {
    __shared__ int soff;
    int i = blockIdx.x * 256 + threadIdx.x;
    if (threadIdx.x == 0) {
        int chunk = blockIdx.x >> 2;
        int acc = 0;
        for (int b = 0; b < chunk; b++) acc += g_bsum[b];
        soff = acc;
    }
    __syncthreads();
    if (i < N_NODES) {
        g_rowptr[i + 1] = g_inc[i] + soff;
        if (i == 0) g_rowptr[0] = 0;
    }
}

__global__ void k_scatter(const int* __restrict__ ei, const float* __restrict__ ea) {
    int e = blockIdx.x * blockDim.x + threadIdx.x;
    if (e >= N_EDGES) return;
    int s = ei[e];
    int d = ei[N_EDGES + e];
    int p = g_rowptr[d] + atomicAdd(&g_cursor[d], 1);
    const float* a = ea + (long long)e * 3;
    g_rec[p] = make_float4(a[0], a[1], a[2], __int_as_float(s));
}

// ---------------- weight pre-rounding to tf32 (once per call) ----------------
__global__ void k_prep(const float* __restrict__ w1, const float* __restrict__ w2) {
    int i = blockIdx.x * blockDim.x + threadIdx.x;
    if (i < LAYERS * HID * HID) {
        g_w1t[i] = wmma::__float_to_tf32(w1[i]);
        g_w2t[i] = wmma::__float_to_tf32(w2[i]);
    }
}

// ---------------- input projection: h = x @ inW + inb ----------------
__global__ void k_inproj(const float* __restrict__ x, const float* __restrict__ inW,
                         const float* __restrict__ inb) {
    int idx = blockIdx.x * blockDim.x + threadIdx.x;
    if (idx >= N_NODES * HID) return;
    int n = idx >> 7, j = idx & 127;
    const float* xr = x + n * 7;
    float s = inb[j];
#pragma unroll
    for (int k = 0; k < 7; k++) s = fmaf(xr[k], inW[k * HID + j], s);
    g_h[idx] = s;
}

// ---------------- edge aggregation: warp/node, float4, 2x unrolled ----------------
// u[n] = tf32round( h[n] + sum_{e: dst=n} relu( h[src_e] + ea_e @ edgeW + edgeb ) )
__global__ void k_edge_agg(const float* __restrict__ edgeW_l, const float* __restrict__ edgeb_l) {
    int warp = threadIdx.x >> 5, lane = threadIdx.x & 31;
    int c0 = lane * 4;
    float4 w0 = *(const float4*)(edgeW_l + 0 * HID + c0);
    float4 w1 = *(const float4*)(edgeW_l + 1 * HID + c0);
    float4 w2 = *(const float4*)(edgeW_l + 2 * HID + c0);
    float4 bb = *(const float4*)(edgeb_l + c0);

    int n = blockIdx.x * 8 + warp;
    if (n >= N_NODES) return;

    int r0 = g_rowptr[n], r1 = g_rowptr[n + 1];
    float4 acc = *(const float4*)(g_h + (size_t)n * HID + c0);

    int e = r0;
    for (; e + 1 < r1; e += 2) {
        float4 ra = g_rec[e];
        float4 rb = g_rec[e + 1];
        int sa = __float_as_int(ra.w);
        int sb = __float_as_int(rb.w);
        float4 ha = *(const float4*)(g_h + (size_t)sa * HID + c0);
        float4 hb = *(const float4*)(g_h + (size_t)sb * HID + c0);
        float ax = fmaf(ra.x, w0.x, fmaf(ra.y, w1.x, fmaf(ra.z, w2.x, bb.x))) + ha.x;
        float ay = fmaf(ra.x, w0.y, fmaf(ra.y, w1.y, fmaf(ra.z, w2.y, bb.y))) + ha.y;
        float az = fmaf(ra.x, w0.z, fmaf(ra.y, w1.z, fmaf(ra.z, w2.z, bb.z))) + ha.z;
        float aw = fmaf(ra.x, w0.w, fmaf(ra.y, w1.w, fmaf(ra.z, w2.w, bb.w))) + ha.w;
        float bx = fmaf(rb.x, w0.x, fmaf(rb.y, w1.x, fmaf(rb.z, w2.x, bb.x))) + hb.x;
        float by = fmaf(rb.x, w0.y, fmaf(rb.y, w1.y, fmaf(rb.z, w2.y, bb.y))) + hb.y;
        float bz = fmaf(rb.x, w0.z, fmaf(rb.y, w1.z, fmaf(rb.z, w2.z, bb.z))) + hb.z;
        float bw = fmaf(rb.x, w0.w, fmaf(rb.y, w1.w, fmaf(rb.z, w2.w, bb.w))) + hb.w;
        acc.x += fmaxf(ax, 0.f) + fmaxf(bx, 0.f);
        acc.y += fmaxf(ay, 0.f) + fmaxf(by, 0.f);
        acc.z += fmaxf(az, 0.f) + fmaxf(bz, 0.f);
        acc.w += fmaxf(aw, 0.f) + fmaxf(bw, 0.f);
    }
    if (e < r1) {
        float4 ra = g_rec[e];
        int sa = __float_as_int(ra.w);
        float4 ha = *(const float4*)(g_h + (size_t)sa * HID + c0);
        float ax = fmaf(ra.x, w0.x, fmaf(ra.y, w1.x, fmaf(ra.z, w2.x, bb.x))) + ha.x;
        float ay = fmaf(ra.x, w0.y, fmaf(ra.y, w1.y, fmaf(ra.z, w2.y, bb.y))) + ha.y;
        float az = fmaf(ra.x, w0.z, fmaf(ra.y, w1.z, fmaf(ra.z, w2.z, bb.z))) + ha.z;
        float aw = fmaf(ra.x, w0.w, fmaf(ra.y, w1.w, fmaf(ra.z, w2.w, bb.w))) + ha.w;
        acc.x += fmaxf(ax, 0.f);
        acc.y += fmaxf(ay, 0.f);
        acc.z += fmaxf(az, 0.f);
        acc.w += fmaxf(aw, 0.f);
    }
    float4 o;
    o.x = wmma::__float_to_tf32(acc.x);
    o.y = wmma::__float_to_tf32(acc.y);
    o.z = wmma::__float_to_tf32(acc.z);
    o.w = wmma::__float_to_tf32(acc.w);
    *(float4*)(g_u + (size_t)n * HID + c0) = o;
}

// ---------------- fused persistent layer: GEMM1+relu -> GEMM2 -> residual+LN ----------------
// 8 warps. W1 fragments (warp's 16-col slice, all 16 k-steps) live in registers.
// W2 staged once into smem; intermediate t never leaves smem.
__global__ void __launch_bounds__(256, 2) k_layer_p(int l,
        const float* __restrict__ b1, const float* __restrict__ b2,
        const float* __restrict__ gamma, const float* __restrict__ beta) {
    const float* W1 = g_w1t + l * HID * HID;
    const float* W2 = g_w2t + l * HID * HID;
    int tid = threadIdx.x, warp = tid >> 5, lane = tid & 31;

    extern __shared__ float smem[];
    float* W2s = smem;                 // 128 x SMW2
    float* As  = smem + W2S_F;         // 16 x SMA
    float* Ts  = As + TILE_F;          // 16 x SMA
    float* Cs  = Ts + TILE_F;          // 16 x SMA

    // W1 fragments in registers (loaded once per block)
    wmma::fragment<wmma::matrix_b, 16, 16, 8, wmma::precision::tf32, wmma::row_major> bf1[16];
#pragma unroll
    for (int k0 = 0; k0 < 16; k0++)
        wmma::load_matrix_sync(bf1[k0], W1 + k0 * 8 * HID + warp * 16, HID);

    // stage W2 into smem (float4)
    const float4* w2src = (const float4*)W2;
    for (int i = tid; i < 128 * 32; i += 256) {
        int r = i >> 5, c = i & 31;
        *(float4*)(W2s + r * SMW2 + c * 4) = w2src[i];
    }

    int c0 = lane * 4;
    float4 b1v  = *(const float4*)(b1 + c0);
    float4 b2v  = *(const float4*)(b2 + c0);
    float4 gam4 = *(const float4*)(gamma + c0);
    float4 bet4 = *(const float4*)(beta  + c0);
    __syncthreads();

    wmma::fragment<wmma::accumulator, 16, 16, 8, float> acc;
    wmma::fragment<wmma::matrix_a, 16, 16, 8, wmma::precision::tf32, wmma::row_major> af;
    wmma::fragment<wmma::matrix_b, 16, 16, 8, wmma::precision::tf32, wmma::row_major> bf2;

    for (int t = blockIdx.x; t < N_TILES; t += gridDim.x) {
        int row0 = t * 16;
        const float4* src = (const float4*)(g_u + (size_t)row0 * HID);
#pragma unroll
        for (int i = tid; i < 512; i += 256) {
            int r = i >> 5, c = i & 31;
            *(float4*)(As + r * SMA + c * 4) = src[i];
        }
        __syncthreads();

        // ---- GEMM1 ----
        wmma::fill_fragment(acc, 0.f);
#pragma unroll
        for (int k0 = 0; k0 < 16; k0++) {
            wmma::load_matrix_sync(af, As + k0 * 8, SMA);
            wmma::mma_sync(acc, af, bf1[k0], acc);
        }
        wmma::store_matrix_sync(Ts + warp * 16, acc, SMA, wmma::mem_row_major);
        __syncthreads();

        // bias1 + relu + tf32 round, in smem
#pragma unroll
        for (int i = tid; i < 512; i += 256) {
            int r = i >> 5, c4 = i & 31;
            float4 v = *(float4*)(Ts + r * SMA + c4 * 4);
            const float* bp = b1 + c4 * 4;
            v.x = wmma::__float_to_tf32(fmaxf(v.x + bp[0], 0.f));
            v.y = wmma::__float_to_tf32(fmaxf(v.y + bp[1], 0.f));
            v.z = wmma::__float_to_tf32(fmaxf(v.z + bp[2], 0.f));
            v.w = wmma::__float_to_tf32(fmaxf(v.w + bp[3], 0.f));
            *(float4*)(Ts + r * SMA + c4 * 4) = v;
        }
        __syncthreads();

        // ---- GEMM2 ----
        wmma::fill_fragment(acc, 0.f);
#pragma unroll
        for (int k0 = 0; k0 < 16; k0++) {
            wmma::load_matrix_sync(af, Ts + k0 * 8, SMA);
            wmma::load_matrix_sync(bf2, W2s + k0 * 8 * SMW2 + warp * 16, SMW2);
            wmma::mma_sync(acc, af, bf2, acc);
        }
        wmma::store_matrix_sync(Cs + warp * 16, acc, SMA, wmma::mem_row_major);
        __syncthreads();

        // ---- residual + LN: warp handles rows {2*warp, 2*warp+1} ----
#pragma unroll
        for (int s = 0; s < 2; s++) {
            int r = warp * 2 + s;
            int grow = row0 + r;
            float4 cv = *(float4*)(Cs + r * SMA + c0);
            float4 hv = *(const float4*)(g_h + (size_t)grow * HID + c0);
            float4 v;
            v.x = hv.x + fmaxf(cv.x + b2v.x, 0.f);
            v.y = hv.y + fmaxf(cv.y + b2v.y, 0.f);
            v.z = hv.z + fmaxf(cv.z + b2v.z, 0.f);
            v.w = hv.w + fmaxf(cv.w + b2v.w, 0.f);
            float sum = v.x + v.y + v.z + v.w;
            float sq  = v.x * v.x + v.y * v.y + v.z * v.z + v.w * v.w;
#pragma unroll
            for (int off = 16; off; off >>= 1) {
                sum += __shfl_xor_sync(0xffffffffu, sum, off);
                sq  += __shfl_xor_sync(0xffffffffu, sq,  off);
            }
            float mu = sum * (1.f / HID);
            float var = sq * (1.f / HID) - mu * mu;
            float rstd = rsqrtf(var + LN_EPS);
            float4 o;
            o.x = (v.x - mu) * rstd * gam4.x + bet4.x;
            o.y = (v.y - mu) * rstd * gam4.y + bet4.y;
            o.z = (v.z - mu) * rstd * gam4.z + bet4.z;
            o.w = (v.w - mu) * rstd * gam4.w + bet4.w;
            *(float4*)(g_h + (size_t)grow * HID + c0) = o;
        }
        __syncthreads();
    }
}

// ---------------- global mean pool (batch sorted -> binary search) ----------------
__device__ __forceinline__ int lbound(const int* a, int n, int key) {
    int lo = 0, hi = n;
    while (lo < hi) { int m = (lo + hi) >> 1; if (a[m] < key) lo = m + 1; else hi = m; }
    return lo;
}

__global__ void k_pool(const int* __restrict__ batch) {
    int g = blockIdx.x, t = threadIdx.x;
    __shared__ int slo, shi;
    if (t == 0) { slo = lbound(batch, N_NODES, g); shi = lbound(batch, N_NODES, g + 1); }
    __syncthreads();
    int lo = slo, hi = shi;
    float s = 0.f;
    for (int n = lo; n < hi; n++) s += g_h[(size_t)n * HID + t];
    float cnt = (float)(hi - lo);
    g_pooled[g * HID + t] = s / fmaxf(cnt, 1.f);
}

// ---------------- MLP head ----------------
__global__ void k_head(const float* __restrict__ W1, const float* __restrict__ b1,
                       const float* __restrict__ W2, const float* __restrict__ b2,
                       const float* __restrict__ W3, const float* __restrict__ b3,
                       float* __restrict__ out) {
    int g = blockIdx.x, t = threadIdx.x;
    __shared__ float p[HID], o1[HID], o2[64], red[64];
    p[t] = g_pooled[g * HID + t];
    __syncthreads();
    float s = b1[t];
    for (int k = 0; k < HID; k++) s = fmaf(p[k], W1[k * HID + t], s);
    o1[t] = fmaxf(s, 0.f);
    __syncthreads();
    if (t < 64) {
        float s2 = b2[t];
        for (int k = 0; k < HID; k++) s2 = fmaf(o1[k], W2[k * 64 + t], s2);
        o2[t] = fmaxf(s2, 0.f);
    }
    __syncthreads();
    if (t < 64) red[t] = o2[t] * W3[t];
    __syncthreads();
    if (t < 32) {
        float v = red[t] + red[t + 32];
#pragma unroll
        for (int off = 16; off; off >>= 1) v += __shfl_down_sync(0xffffffffu, v, off);
        if (t == 0) out[g] = v + b3[0];
    }
}

// ---------------- launch ----------------
extern "C" void kernel_launch(void* const* d_in, const int* in_sizes, int n_in,
                              void* d_out, int out_size) {
    const float* x     = (const float*)d_in[0];
    const int*   ei    = (const int*)  d_in[1];
    const float* ea    = (const float*)d_in[2];
    const int*   batch = (const int*)  d_in[3];
    const float* inW   = (const float*)d_in[4];
    const float* inb   = (const float*)d_in[5];
    const float* edgeW = (const float*)d_in[6];
    const float* edgeb = (const float*)d_in[7];
    const float* w1    = (const float*)d_in[8];
    const float* b1    = (const float*)d_in[9];
    const float* w2    = (const float*)d_in[10];
    const float* b2    = (const float*)d_in[11];
    const float* gamma = (const float*)d_in[12];
    const float* beta  = (const float*)d_in[13];
    const float* fcW1  = (const float*)d_in[14];
    const float* fcb1  = (const float*)d_in[15];
    const float* fcW2  = (const float*)d_in[16];
    const float* fcb2  = (const float*)d_in[17];
    const float* fcW3  = (const float*)d_in[18];
    const float* fcb3  = (const float*)d_in[19];
    float* out = (float*)d_out;

    static int smem_set = 0;
    if (!smem_set) {
        cudaFuncSetAttribute(k_layer_p, cudaFuncAttributeMaxDynamicSharedMemorySize, SMEM_B);
        smem_set = 1;
    }

    k_zero<<<(N_NODES + 255) / 256, 256>>>();
    k_hist<<<(N_EDGES + 255) / 256, 256>>>(ei);
    k_scanA<<<98, 1024>>>();
    k_scanBC<<<(N_NODES + 255) / 256, 256>>>();
    k_scatter<<<(N_EDGES + 255) / 256, 256>>>(ei, ea);
    k_prep<<<(LAYERS * HID * HID + 255) / 256, 256>>>(w1, w2);
    k_inproj<<<(N_NODES * HID + 255) / 256, 256>>>(x, inW, inb);

    for (int l = 0; l < 4; l++) {
        k_edge_agg<<<(N_NODES + 7) / 8, 256>>>(edgeW + l * 3 * HID, edgeb + l * HID);
        k_layer_p<<<GGRID, 256, SMEM_B>>>(l, b1 + l * HID, b2 + l * HID,
                                          gamma + l * HID, beta + l * HID);
    }

    k_pool<<<NGRAPH, 128>>>(batch);
    k_head<<<NGRAPH, 128>>>(fcW1, fcb1, fcW2, fcb2, fcW3, fcb3, out);
}

// round 7
// speedup vs baseline: 1.4237x; 1.0130x over previous
#include <cuda_runtime.h>
#include <mma.h>

using namespace nvcuda;

#define N_NODES   100000
#define NODES_PAD 100096            // 3128 * 32
#define N_TILES32 3128              // NODES_PAD / 32
#define N_EDGES   1600000
#define HID       128
#define NGRAPH    1024
#define LN_EPS    1e-5f
#define SCAN_PAD  100352            // 98 * 1024
#define LAYERS    4
#define GGRID     296               // persistent GEMM grid
#define SMA       136               // smem A/T row stride (floats)
#define SMW2      132               // smem W2 row stride (floats)

// dynamic smem (floats): W2s[128*SMW2] | As[32*SMA] (aliased as Cs) | Ts[32*SMA]
#define W2S_F     (128 * SMW2)                       // 16896
#define TILE_F    (32 * SMA)                         // 4352
#define SMEM_F    (W2S_F + 2 * TILE_F)               // 25600
#define SMEM_B    (SMEM_F * 4)                       // 102,400 bytes

// ---------------- scratch (static __device__, allocation-free) ----------------
__device__ float  g_h[NODES_PAD * HID];    // node features fp32
__device__ float  g_u[NODES_PAD * HID];    // agg + h (tf32-rounded); pad rows stay 0
__device__ float  g_w1t[LAYERS * HID * HID];
__device__ float  g_w2t[LAYERS * HID * HID];
__device__ float4 g_rec[N_EDGES];          // packed edge: ea0,ea1,ea2,src(bits)
__device__ int    g_deg[N_NODES];
__device__ int    g_inc[SCAN_PAD];
__device__ int    g_bsum[128];
__device__ int    g_rowptr[N_NODES + 1];
__device__ int    g_cursor[N_NODES];
__device__ float  g_pooled[NGRAPH * HID];

// ---------------- CSR build ----------------
__global__ void k_zero() {
    int i = blockIdx.x * blockDim.x + threadIdx.x;
    if (i < N_NODES) { g_deg[i] = 0; g_cursor[i] = 0; }
}

__global__ void k_hist(const int* __restrict__ ei) {
    int e = blockIdx.x * blockDim.x + threadIdx.x;
    if (e < N_EDGES) atomicAdd(&g_deg[ei[N_EDGES + e]], 1);
}

__global__ void k_scanA() {
    __shared__ int s[1024];
    int t = threadIdx.x;
    int i = blockIdx.x * 1024 + t;
    int v = (i < N_NODES) ? g_deg[i] : 0;
    s[t] = v;
    __syncthreads();
    for (int off = 1; off < 1024; off <<= 1) {
        int w = (t >= off) ? s[t - off] : 0;
        __syncthreads();
        s[t] += w;
        __syncthreads();
    }
    g_inc[i] = s[t];
    if (t == 1023) g_bsum[blockIdx.x] = s[1023];
}

__global__ void k_scanBC() {
    __shared__ int soff;
    int i = blockIdx.x * 256 + threadIdx.x;
    if (threadIdx.x == 0) {
        int chunk = blockIdx.x >> 2;
        int acc = 0;
        for (int b = 0; b < chunk; b++) acc += g_bsum[b];
        soff = acc;
    }
    __syncthreads();
    if (i < N_NODES) {
        g_rowptr[i + 1] = g_inc[i] + soff;
        if (i == 0) g_rowptr[0] = 0;
    }
}

__global__ void k_scatter(const int* __restrict__ ei, const float* __restrict__ ea) {
    int e = blockIdx.x * blockDim.x + threadIdx.x;
    if (e >= N_EDGES) return;
    int s = ei[e];
    int d = ei[N_EDGES + e];
    int p = g_rowptr[d] + atomicAdd(&g_cursor[d], 1);
    const float* a = ea + (long long)e * 3;
    g_rec[p] = make_float4(a[0], a[1], a[2], __int_as_float(s));
}

// ---------------- weight pre-rounding to tf32 (once per call) ----------------
__global__ void k_prep(const float* __restrict__ w1, const float* __restrict__ w2) {
    int i = blockIdx.x * blockDim.x + threadIdx.x;
    if (i < LAYERS * HID * HID) {
        g_w1t[i] = wmma::__float_to_tf32(w1[i]);
        g_w2t[i] = wmma::__float_to_tf32(w2[i]);
    }
}

// ---------------- input projection: h = x @ inW + inb ----------------
__global__ void k_inproj(const float* __restrict__ x, const float* __restrict__ inW,
                         const float* __restrict__ inb) {
    int idx = blockIdx.x * blockDim.x + threadIdx.x;
    if (idx >= N_NODES * HID) return;
    int n = idx >> 7, j = idx & 127;
    const float* xr = x + n * 7;
    float s = inb[j];
#pragma unroll
    for (int k = 0; k < 7; k++) s = fmaf(xr[k], inW[k * HID + j], s);
    g_h[idx] = s;
}

// ---------------- edge aggregation: warp/node, float4, 4-deep load pipeline ----------------
struct EW { float4 w0, w1, w2, bb; };

__device__ __forceinline__ void edge_acc(float4& acc, const float4& r, const float4& hv,
                                         const EW& W) {
    float mx = fmaf(r.x, W.w0.x, fmaf(r.y, W.w1.x, fmaf(r.z, W.w2.x, W.bb.x))) + hv.x;
    float my = fmaf(r.x, W.w0.y, fmaf(r.y, W.w1.y, fmaf(r.z, W.w2.y, W.bb.y))) + hv.y;
    float mz = fmaf(r.x, W.w0.z, fmaf(r.y, W.w1.z, fmaf(r.z, W.w2.z, W.bb.z))) + hv.z;
    float mw = fmaf(r.x, W.w0.w, fmaf(r.y, W.w1.w, fmaf(r.z, W.w2.w, W.bb.w))) + hv.w;
    acc.x += fmaxf(mx, 0.f);
    acc.y += fmaxf(my, 0.f);
    acc.z += fmaxf(mz, 0.f);
    acc.w += fmaxf(mw, 0.f);
}

__global__ void k_edge_agg(const float* __restrict__ edgeW_l, const float* __restrict__ edgeb_l) {
    int warp = threadIdx.x >> 5, lane = threadIdx.x & 31;
    int c0 = lane * 4;
    EW W;
    W.w0 = *(const float4*)(edgeW_l + 0 * HID + c0);
    W.w1 = *(const float4*)(edgeW_l + 1 * HID + c0);
    W.w2 = *(const float4*)(edgeW_l + 2 * HID + c0);
    W.bb = *(const float4*)(edgeb_l + c0);

    int n = blockIdx.x * 8 + warp;
    if (n >= N_NODES) return;

    int r0 = g_rowptr[n], r1 = g_rowptr[n + 1];
    float4 acc = *(const float4*)(g_h + (size_t)n * HID + c0);

    int e = r0;
    for (; e + 3 < r1; e += 4) {
        // 4 independent record loads (sequential addresses)
        float4 ra = g_rec[e];
        float4 rb = g_rec[e + 1];
        float4 rc = g_rec[e + 2];
        float4 rd = g_rec[e + 3];
        // 4 independent gather loads
        float4 ha = *(const float4*)(g_h + (size_t)__float_as_int(ra.w) * HID + c0);
        float4 hb = *(const float4*)(g_h + (size_t)__float_as_int(rb.w) * HID + c0);
        float4 hc = *(const float4*)(g_h + (size_t)__float_as_int(rc.w) * HID + c0);
        float4 hd = *(const float4*)(g_h + (size_t)__float_as_int(rd.w) * HID + c0);
        edge_acc(acc, ra, ha, W);
        edge_acc(acc, rb, hb, W);
        edge_acc(acc, rc, hc, W);
        edge_acc(acc, rd, hd, W);
    }
    for (; e < r1; e++) {
        float4 ra = g_rec[e];
        float4 ha = *(const float4*)(g_h + (size_t)__float_as_int(ra.w) * HID + c0);
        edge_acc(acc, ra, ha, W);
    }
    float4 o;
    o.x = wmma::__float_to_tf32(acc.x);
    o.y = wmma::__float_to_tf32(acc.y);
    o.z = wmma::__float_to_tf32(acc.z);
    o.w = wmma::__float_to_tf32(acc.w);
    *(float4*)(g_u + (size_t)n * HID + c0) = o;
}

// ---------------- fused persistent layer, 32-row tiles ----------------
// 8 warps; warp owns a 16-col slice with W1 fragments in regs and 2 row-tile accumulators.
__global__ void __launch_bounds__(256, 2) k_layer_p(int l,
        const float* __restrict__ b1, const float* __restrict__ b2,
        const float* __restrict__ gamma, const float* __restrict__ beta) {
    const float* W1 = g_w1t + l * HID * HID;
    const float* W2 = g_w2t + l * HID * HID;
    int tid = threadIdx.x, warp = tid >> 5, lane = tid & 31;

    extern __shared__ float smem[];
    float* W2s = smem;                 // 128 x SMW2
    float* As  = smem + W2S_F;         // 32 x SMA  (reused as Cs after GEMM1)
    float* Ts  = As + TILE_F;          // 32 x SMA
    float* Cs  = As;                   // alias

    wmma::fragment<wmma::matrix_b, 16, 16, 8, wmma::precision::tf32, wmma::row_major> bf1[16];
#pragma unroll
    for (int k0 = 0; k0 < 16; k0++)
        wmma::load_matrix_sync(bf1[k0], W1 + k0 * 8 * HID + warp * 16, HID);

    const float4* w2src = (const float4*)W2;
    for (int i = tid; i < 128 * 32; i += 256) {
        int r = i >> 5, c = i & 31;
        *(float4*)(W2s + r * SMW2 + c * 4) = w2src[i];
    }

    int c0 = lane * 4;
    float4 b2v  = *(const float4*)(b2 + c0);
    float4 gam4 = *(const float4*)(gamma + c0);
    float4 bet4 = *(const float4*)(beta  + c0);
    __syncthreads();

    wmma::fragment<wmma::accumulator, 16, 16, 8, float> acc0, acc1;
    wmma::fragment<wmma::matrix_a, 16, 16, 8, wmma::precision::tf32, wmma::row_major> af0, af1;
    wmma::fragment<wmma::matrix_b, 16, 16, 8, wmma::precision::tf32, wmma::row_major> bf2;

    for (int t = blockIdx.x; t < N_TILES32; t += gridDim.x) {
        int row0 = t * 32;
        const float4* src = (const float4*)(g_u + (size_t)row0 * HID);
#pragma unroll
        for (int i = tid; i < 1024; i += 256) {
            int r = i >> 5, c = i & 31;
            *(float4*)(As + r * SMA + c * 4) = src[i];
        }
        __syncthreads();

        // ---- GEMM1 (two row-tiles per warp) ----
        wmma::fill_fragment(acc0, 0.f);
        wmma::fill_fragment(acc1, 0.f);
#pragma unroll
        for (int k0 = 0; k0 < 16; k0++) {
            wmma::load_matrix_sync(af0, As + k0 * 8, SMA);
            wmma::load_matrix_sync(af1, As + 16 * SMA + k0 * 8, SMA);
            wmma::mma_sync(acc0, af0, bf1[k0], acc0);
            wmma::mma_sync(acc1, af1, bf1[k0], acc1);
        }
        wmma::store_matrix_sync(Ts + warp * 16, acc0, SMA, wmma::mem_row_major);
        wmma::store_matrix_sync(Ts + 16 * SMA + warp * 16, acc1, SMA, wmma::mem_row_major);
        __syncthreads();

        // bias1 + relu + tf32 round, in smem
#pragma unroll
        for (int i = tid; i < 1024; i += 256) {
            int r = i >> 5, c4 = i & 31;
            float4 v = *(float4*)(Ts + r * SMA + c4 * 4);
            const float* bp = b1 + c4 * 4;
            v.x = wmma::__float_to_tf32(fmaxf(v.x + bp[0], 0.f));
            v.y = wmma::__float_to_tf32(fmaxf(v.y + bp[1], 0.f));
            v.z = wmma::__float_to_tf32(fmaxf(v.z + bp[2], 0.f));
            v.w = wmma::__float_to_tf32(fmaxf(v.w + bp[3], 0.f));
            *(float4*)(Ts + r * SMA + c4 * 4) = v;
        }
        __syncthreads();

        // ---- GEMM2 ----
        wmma::fill_fragment(acc0, 0.f);
        wmma::fill_fragment(acc1, 0.f);
#pragma unroll
        for (int k0 = 0; k0 < 16; k0++) {
            wmma::load_matrix_sync(bf2, W2s + k0 * 8 * SMW2 + warp * 16, SMW2);
            wmma::load_matrix_sync(af0, Ts + k0 * 8, SMA);
            wmma::load_matrix_sync(af1, Ts + 16 * SMA + k0 * 8, SMA);
            wmma::mma_sync(acc0, af0, bf2, acc0);
            wmma::mma_sync(acc1, af1, bf2, acc1);
        }
        wmma::store_matrix_sync(Cs + warp * 16, acc0, SMA, wmma::mem_row_major);
        wmma::store_matrix_sync(Cs + 16 * SMA + warp * 16, acc1, SMA, wmma::mem_row_major);
        __syncthreads();

        // ---- residual + LN: warp handles rows 4*warp .. 4*warp+3 ----
#pragma unroll
        for (int s = 0; s < 4; s++) {
            int r = warp * 4 + s;
            int grow = row0 + r;
            float4 cv = *(float4*)(Cs + r * SMA + c0);
            float4 hv = *(const float4*)(g_h + (size_t)grow * HID + c0);
            float4 v;
            v.x = hv.x + fmaxf(cv.x + b2v.x, 0.f);
            v.y = hv.y + fmaxf(cv.y + b2v.y, 0.f);
            v.z = hv.z + fmaxf(cv.z + b2v.z, 0.f);
            v.w = hv.w + fmaxf(cv.w + b2v.w, 0.f);
            float sum = v.x + v.y + v.z + v.w;
            float sq  = v.x * v.x + v.y * v.y + v.z * v.z + v.w * v.w;
#pragma unroll
            for (int off = 16; off; off >>= 1) {
                sum += __shfl_xor_sync(0xffffffffu, sum, off);
                sq  += __shfl_xor_sync(0xffffffffu, sq,  off);
            }
            float mu = sum * (1.f / HID);
            float var = sq * (1.f / HID) - mu * mu;
            float rstd = rsqrtf(var + LN_EPS);
            float4 o;
            o.x = (v.x - mu) * rstd * gam4.x + bet4.x;
            o.y = (v.y - mu) * rstd * gam4.y + bet4.y;
            o.z = (v.z - mu) * rstd * gam4.z + bet4.z;
            o.w = (v.w - mu) * rstd * gam4.w + bet4.w;
            *(float4*)(g_h + (size_t)grow * HID + c0) = o;
        }
        __syncthreads();
    }
}

// ---------------- global mean pool (batch sorted -> binary search) ----------------
__device__ __forceinline__ int lbound(const int* a, int n, int key) {
    int lo = 0, hi = n;
    while (lo < hi) { int m = (lo + hi) >> 1; if (a[m] < key) lo = m + 1; else hi = m; }
    return lo;
}

__global__ void k_pool(const int* __restrict__ batch) {
    int g = blockIdx.x, t = threadIdx.x;
    __shared__ int slo, shi;
    if (t == 0) { slo = lbound(batch, N_NODES, g); shi = lbound(batch, N_NODES, g + 1); }
    __syncthreads();
    int lo = slo, hi = shi;
    float s = 0.f;
    for (int n = lo; n < hi; n++) s += g_h[(size_t)n * HID + t];
    float cnt = (float)(hi - lo);
    g_pooled[g * HID + t] = s / fmaxf(cnt, 1.f);
}

// ---------------- MLP head ----------------
__global__ void k_head(const float* __restrict__ W1, const float* __restrict__ b1,
                       const float* __restrict__ W2, const float* __restrict__ b2,
                       const float* __restrict__ W3, const float* __restrict__ b3,
                       float* __restrict__ out) {
    int g = blockIdx.x, t = threadIdx.x;
    __shared__ float p[HID], o1[HID], o2[64], red[64];
    p[t] = g_pooled[g * HID + t];
    __syncthreads();
    float s = b1[t];
    for (int k = 0; k < HID; k++) s = fmaf(p[k], W1[k * HID + t], s);
    o1[t] = fmaxf(s, 0.f);
    __syncthreads();
    if (t < 64) {
        float s2 = b2[t];
        for (int k = 0; k < HID; k++) s2 = fmaf(o1[k], W2[k * 64 + t], s2);
        o2[t] = fmaxf(s2, 0.f);
    }
    __syncthreads();
    if (t < 64) red[t] = o2[t] * W3[t];
    __syncthreads();
    if (t < 32) {
        float v = red[t] + red[t + 32];
#pragma unroll
        for (int off = 16; off; off >>= 1) v += __shfl_down_sync(0xffffffffu, v, off);
        if (t == 0) out[g] = v + b3[0];
    }
}

// ---------------- launch ----------------
extern "C" void kernel_launch(void* const* d_in, const int* in_sizes, int n_in,
                              void* d_out, int out_size) {
    const float* x     = (const float*)d_in[0];
    const int*   ei    = (const int*)  d_in[1];
    const float* ea    = (const float*)d_in[2];
    const int*   batch = (const int*)  d_in[3];
    const float* inW   = (const float*)d_in[4];
    const float* inb   = (const float*)d_in[5];
    const float* edgeW = (const float*)d_in[6];
    const float* edgeb = (const float*)d_in[7];
    const float* w1    = (const float*)d_in[8];
    const float* b1    = (const float*)d_in[9];
    const float* w2    = (const float*)d_in[10];
    const float* b2    = (const float*)d_in[11];
    const float* gamma = (const float*)d_in[12];
    const float* beta  = (const float*)d_in[13];
    const float* fcW1  = (const float*)d_in[14];
    const float* fcb1  = (const float*)d_in[15];
    const float* fcW2  = (const float*)d_in[16];
    const float* fcb2  = (const float*)d_in[17];
    const float* fcW3  = (const float*)d_in[18];
    const float* fcb3  = (const float*)d_in[19];
    float* out = (float*)d_out;

    static int smem_set = 0;
    if (!smem_set) {
        cudaFuncSetAttribute(k_layer_p, cudaFuncAttributeMaxDynamicSharedMemorySize, SMEM_B);
        smem_set = 1;
    }

    k_zero<<<(N_NODES + 255) / 256, 256>>>();
    k_hist<<<(N_EDGES + 255) / 256, 256>>>(ei);
    k_scanA<<<98, 1024>>>();
    k_scanBC<<<(N_NODES + 255) / 256, 256>>>();
    k_scatter<<<(N_EDGES + 255) / 256, 256>>>(ei, ea);
    k_prep<<<(LAYERS * HID * HID + 255) / 256, 256>>>(w1, w2);
    k_inproj<<<(N_NODES * HID + 255) / 256, 256>>>(x, inW, inb);

    for (int l = 0; l < 4; l++) {
        k_edge_agg<<<(N_NODES + 7) / 8, 256>>>(edgeW + l * 3 * HID, edgeb + l * HID);
        k_layer_p<<<GGRID, 256, SMEM_B>>>(l, b1 + l * HID, b2 + l * HID,
                                          gamma + l * HID, beta + l * HID);
    }

    k_pool<<<NGRAPH, 128>>>(batch);
    k_head<<<NGRAPH, 128>>>(fcW1, fcb1, fcW2, fcb2, fcW3, fcb3, out);
}